// round 7
// baseline (speedup 1.0000x reference)
#include <cuda_runtime.h>
#include <cstdint>
#include <cstddef>

#define NROWS 16384
#define DM    1024
#define DF    4096

#define BM 128
#define BN 256
#define BK 32
#define NBUF 4
#define A_BYTES (BM * BK * 4)          // 16384
#define B_BYTES (BN * BK * 4)          // 32768
#define STAGE_BYTES (A_BYTES + B_BYTES) // 49152
#define SM_STAGE_OFF 1024
#define SMEM_BYTES (SM_STAGE_OFF + NBUF * STAGE_BYTES) // 197632

// Scratch (allocation-free rule: __device__ globals)
__device__ float g_x[(size_t)NROWS * DM];
__device__ float g_w1[(size_t)DF * DM];
__device__ float g_w2[(size_t)DM * DF];
__device__ float g_inner[(size_t)NROWS * DF];
__device__ float g_part[(size_t)4 * NROWS];

static __device__ __forceinline__ uint32_t smem_u32(const void* p) {
    uint32_t a;
    asm("{ .reg .u64 t; cvta.to.shared.u64 t, %1; cvt.u32.u64 %0, t; }" : "=r"(a) : "l"(p));
    return a;
}
static __device__ __forceinline__ void cp16(uint32_t dst, const void* src) {
    asm volatile("cp.async.cg.shared.global [%0], [%1], 16;" :: "r"(dst), "l"(src) : "memory");
}
static __device__ __forceinline__ void cp_commit() {
    asm volatile("cp.async.commit_group;" ::: "memory");
}
static __device__ __forceinline__ void cp_wait2() {
    asm volatile("cp.async.wait_group 2;" ::: "memory");
}
static __device__ __forceinline__ float rna_tf32(float v) {
    uint32_t u;
    asm("cvt.rna.tf32.f32 %0, %1;" : "=r"(u) : "f"(v));
    return __uint_as_float(u);
}
static __device__ __forceinline__ void mma_tf32(float* d, const uint32_t* a, const uint32_t* b) {
    asm volatile(
        "mma.sync.aligned.m16n8k8.row.col.f32.tf32.tf32.f32 "
        "{%0,%1,%2,%3}, {%4,%5,%6,%7}, {%8,%9}, {%0,%1,%2,%3};"
        : "+f"(d[0]), "+f"(d[1]), "+f"(d[2]), "+f"(d[3])
        : "r"(a[0]), "r"(a[1]), "r"(a[2]), "r"(a[3]), "r"(b[0]), "r"(b[1]));
}
static __device__ __forceinline__ float fast_tanh(float x) {
    return 1.0f - 2.0f / (1.0f + __expf(2.0f * x));
}

// Load one k-stage (A: BM x BK, B: BN x BK) into swizzled smem via cp.async.
template <int KD>
static __device__ __forceinline__ void load_stage(char* sm, int buf, const float* A,
                                                  const float* W, int m0, int n0,
                                                  int kt, int tid) {
    char* base = sm + SM_STAGE_OFF + buf * STAGE_BYTES;
    const float* asrc = A + (size_t)m0 * KD + (size_t)kt * BK;
    const float* bsrc = W + (size_t)n0 * KD + (size_t)kt * BK;
#pragma unroll
    for (int j = 0; j < 4; j++) {                       // A: 1024 16B chunks
        int i = tid + j * 256;
        int row = i >> 3, jj = i & 7;
        uint32_t woff = row * 32 + ((jj * 4) ^ ((row & 7) * 4));
        cp16(smem_u32(base + woff * 4), asrc + (size_t)row * KD + jj * 4);
    }
#pragma unroll
    for (int j = 0; j < 8; j++) {                       // B: 2048 16B chunks
        int i = tid + j * 256;
        int row = i >> 3, jj = i & 7;
        uint32_t woff = row * 32 + ((jj * 4) ^ ((row & 7) * 4));
        cp16(smem_u32(base + A_BYTES + woff * 4), bsrc + (size_t)row * KD + jj * 4);
    }
    cp_commit();
}

// MODE 1: g_inner = rna_tf32(tanh(A@W^T + bias)); MODE 2: g_part += rowdot(tanh(...), X)
template <int KD, int MODE>
__global__ void __launch_bounds__(256, 1)
gemm_kernel(const float* __restrict__ A, const float* __restrict__ W,
            const float* __restrict__ bias, const float* __restrict__ X) {
    extern __shared__ char sm[];
    const int tid = threadIdx.x;
    const int lane = tid & 31;
    const int wid = tid >> 5;
    const int wm = wid & 1;        // 2 warps over M (64 rows each)
    const int wn = wid >> 1;       // 4 warps over N (64 cols each)
    const int r = lane >> 2, c = lane & 3;
    const int m0 = blockIdx.y * BM;
    const int n0 = blockIdx.x * BN;
    const int KT = KD / BK;

    // bias slice -> smem [0,1024)
    ((float*)sm)[tid] = bias[n0 + tid];

    float acc[4][8][4];
#pragma unroll
    for (int mt = 0; mt < 4; mt++)
#pragma unroll
        for (int nt = 0; nt < 8; nt++)
#pragma unroll
            for (int q = 0; q < 4; q++) acc[mt][nt][q] = 0.0f;

    load_stage<KD>(sm, 0, A, W, m0, n0, 0, tid);
    load_stage<KD>(sm, 1, A, W, m0, n0, 1, tid);

    for (int kt = 0; kt < KT; kt++) {
        if (kt + 2 < KT) load_stage<KD>(sm, (kt + 2) & 3, A, W, m0, n0, kt + 2, tid);
        else cp_commit();  // keep group accounting uniform
        cp_wait2();
        __syncthreads();

        const uint32_t* As = (const uint32_t*)(sm + SM_STAGE_OFF + (kt & 3) * STAGE_BYTES);
        const uint32_t* Bs = As + A_BYTES / 4;
#pragma unroll
        for (int ks = 0; ks < 4; ks++) {
            uint32_t af[4][4], bf[8][2];
            const int k0 = ks * 8 + c, k1 = k0 + 4;
#pragma unroll
            for (int mt = 0; mt < 4; mt++) {
                int row = wm * 64 + mt * 16 + r;
                int rb = row * 32, sw = (row & 7) * 4;
                af[mt][0] = As[rb + (k0 ^ sw)];
                af[mt][1] = As[rb + 256 + (k0 ^ sw)];
                af[mt][2] = As[rb + (k1 ^ sw)];
                af[mt][3] = As[rb + 256 + (k1 ^ sw)];
            }
#pragma unroll
            for (int nt = 0; nt < 8; nt++) {
                int n = wn * 64 + nt * 8 + r;
                int nb = n * 32, sw = (n & 7) * 4;
                bf[nt][0] = Bs[nb + (k0 ^ sw)];
                bf[nt][1] = Bs[nb + (k1 ^ sw)];
            }
#pragma unroll
            for (int mt = 0; mt < 4; mt++)
#pragma unroll
                for (int nt = 0; nt < 8; nt++)
                    mma_tf32(acc[mt][nt], af[mt], bf[nt]);
        }
    }
    __syncthreads();

    const float* bsm = (const float*)sm;
    if (MODE == 1) {
#pragma unroll
        for (int mt = 0; mt < 4; mt++) {
            int row = m0 + wm * 64 + mt * 16 + r;
#pragma unroll
            for (int nt = 0; nt < 8; nt++) {
                int cl = wn * 64 + nt * 8 + c * 2;   // col within tile
                float2 v0, v1;
                v0.x = rna_tf32(fast_tanh(acc[mt][nt][0] + bsm[cl]));
                v0.y = rna_tf32(fast_tanh(acc[mt][nt][1] + bsm[cl + 1]));
                v1.x = rna_tf32(fast_tanh(acc[mt][nt][2] + bsm[cl]));
                v1.y = rna_tf32(fast_tanh(acc[mt][nt][3] + bsm[cl + 1]));
                *(float2*)(g_inner + (size_t)row * DF + n0 + cl) = v0;
                *(float2*)(g_inner + (size_t)(row + 8) * DF + n0 + cl) = v1;
            }
        }
    } else {
        float rowacc[4][2];
#pragma unroll
        for (int mt = 0; mt < 4; mt++) { rowacc[mt][0] = 0.0f; rowacc[mt][1] = 0.0f; }
#pragma unroll
        for (int mt = 0; mt < 4; mt++) {
            int row = m0 + wm * 64 + mt * 16 + r;
#pragma unroll
            for (int nt = 0; nt < 8; nt++) {
                int cl = wn * 64 + nt * 8 + c * 2;
                float2 x0 = *(const float2*)(X + (size_t)row * DM + n0 + cl);
                float2 x1 = *(const float2*)(X + (size_t)(row + 8) * DM + n0 + cl);
                rowacc[mt][0] += fast_tanh(acc[mt][nt][0] + bsm[cl]) * x0.x
                               + fast_tanh(acc[mt][nt][1] + bsm[cl + 1]) * x0.y;
                rowacc[mt][1] += fast_tanh(acc[mt][nt][2] + bsm[cl]) * x1.x
                               + fast_tanh(acc[mt][nt][3] + bsm[cl + 1]) * x1.y;
            }
        }
        // reduce across the 4 lanes sharing a row (lane groups of 4)
#pragma unroll
        for (int mt = 0; mt < 4; mt++)
#pragma unroll
            for (int h = 0; h < 2; h++) {
                float v = rowacc[mt][h];
                v += __shfl_xor_sync(0xFFFFFFFF, v, 1);
                v += __shfl_xor_sync(0xFFFFFFFF, v, 2);
                rowacc[mt][h] = v;
            }
        float* part = (float*)(sm + SM_STAGE_OFF);  // [128][4], stages are dead now
        if (c == 0) {
#pragma unroll
            for (int mt = 0; mt < 4; mt++) {
                part[(wm * 64 + mt * 16 + r) * 4 + wn] = rowacc[mt][0];
                part[(wm * 64 + mt * 16 + r + 8) * 4 + wn] = rowacc[mt][1];
            }
        }
        __syncthreads();
        if (tid < 128) {
            float s = part[tid * 4] + part[tid * 4 + 1] + part[tid * 4 + 2] + part[tid * 4 + 3];
            g_part[(size_t)blockIdx.x * NROWS + m0 + tid] = s;
        }
    }
}

__global__ void roundcopy_kernel(float* __restrict__ dst, const float* __restrict__ src, int n4) {
    int i = blockIdx.x * blockDim.x + threadIdx.x;
    if (i < n4) {
        float4 v = ((const float4*)src)[i];
        v.x = rna_tf32(v.x); v.y = rna_tf32(v.y);
        v.z = rna_tf32(v.z); v.w = rna_tf32(v.w);
        ((float4*)dst)[i] = v;
    }
}

__global__ void finalize_kernel(float* __restrict__ out) {
    int i = blockIdx.x * blockDim.x + threadIdx.x;
    if (i < NROWS) {
        float s = g_part[i] + g_part[NROWS + i] + g_part[2 * NROWS + i] + g_part[3 * NROWS + i];
        out[i] = 1.0f / (1.0f + __expf(-s));
    }
}

extern "C" void kernel_launch(void* const* d_in, const int* in_sizes, int n_in,
                              void* d_out, int out_size) {
    const float* X  = (const float*)d_in[0];
    const float* W1 = (const float*)d_in[1];
    const float* b1 = (const float*)d_in[2];
    const float* W2 = (const float*)d_in[3];
    const float* b2 = (const float*)d_in[4];

    float *px, *pw1, *pw2, *pin;
    cudaGetSymbolAddress((void**)&px,  g_x);
    cudaGetSymbolAddress((void**)&pw1, g_w1);
    cudaGetSymbolAddress((void**)&pw2, g_w2);
    cudaGetSymbolAddress((void**)&pin, g_inner);

    cudaFuncSetAttribute(gemm_kernel<DM, 1>, cudaFuncAttributeMaxDynamicSharedMemorySize, SMEM_BYTES);
    cudaFuncSetAttribute(gemm_kernel<DF, 2>, cudaFuncAttributeMaxDynamicSharedMemorySize, SMEM_BYTES);

    roundcopy_kernel<<<(NROWS * DM / 4 + 255) / 256, 256>>>(px, X, NROWS * DM / 4);
    roundcopy_kernel<<<(DF * DM / 4 + 255) / 256, 256>>>(pw1, W1, DF * DM / 4);
    roundcopy_kernel<<<(DM * DF / 4 + 255) / 256, 256>>>(pw2, W2, DM * DF / 4);

    // GEMM1: inner = tanh(X @ W1^T + b1), rounded to tf32
    gemm_kernel<DM, 1><<<dim3(DF / BN, NROWS / BM), 256, SMEM_BYTES>>>(px, pw1, b1, nullptr);
    // GEMM2: partial row-dots of tanh(inner @ W2^T + b2) with X
    gemm_kernel<DF, 2><<<dim3(DM / BN, NROWS / BM), 256, SMEM_BYTES>>>(pin, pw2, b2, X);
    finalize_kernel<<<(NROWS + 255) / 256, 256>>>((float*)d_out);
}